// round 4
// baseline (speedup 1.0000x reference)
#include <cuda_runtime.h>
#include <cstdint>

// Problem constants
#define BQ 1024
#define TT 365
#define DD 5
#define SS 27
#define HH 256

// Tiling
#define BT   64    // batch rows per cluster (group)
#define HC   32    // h-columns per CTA (per gate)
#define NCTA 128
#define NTHR 256
#define CLUSTER 8  // CTAs per cluster = 256/32 column tiles

// Padded k layout: k[0..4]=x, k[5..7]=0, k[8..263]=h  -> x part = 2 kq, h part = 64 kq
#define KQX 2
#define KQH 64

// Global hidden state, double buffered (allocation-free scratch)
__device__ float g_h[2][BQ][HH];

// ---- packed fp32x2 helpers (Blackwell FFMA2: 2x fp32 throughput) ----
__device__ __forceinline__ unsigned long long pack2(float lo, float hi) {
    unsigned long long r;
    asm("mov.b64 %0, {%1,%2};" : "=l"(r) : "f"(lo), "f"(hi));
    return r;
}
__device__ __forceinline__ void unpack2(unsigned long long v, float &lo, float &hi) {
    asm("mov.b64 {%0,%1}, %2;" : "=f"(lo), "=f"(hi) : "l"(v));
}
__device__ __forceinline__ void ffma2(unsigned long long &d,
                                      unsigned long long a,
                                      unsigned long long b) {
    asm("fma.rn.f32x2 %0, %1, %2, %0;" : "+l"(d) : "l"(a), "l"(b));
}

__device__ __forceinline__ float sigmoidf_(float x) {
    return 1.f / (1.f + __expf(-x));
}
__device__ __forceinline__ float tanhf_(float x) {
    float e = __expf(-2.f * fabsf(x));
    float r = (1.f - e) / (1.f + e);
    return copysignf(r, x);
}

__device__ __forceinline__ unsigned smem_u32(const void* p) {
    unsigned a;
    asm("{ .reg .u64 t; cvta.to.shared.u64 t, %1; cvt.u32.u64 %0, t; }"
        : "=r"(a) : "l"(p));
    return a;
}

__device__ __forceinline__ void mbar_wait(unsigned mbar, unsigned parity) {
    asm volatile(
        "{\n\t.reg .pred P;\n"
        "W_%=:\n\t"
        "mbarrier.try_wait.parity.acquire.cta.shared::cta.b64 P, [%0], %1, 0x989680;\n\t"
        "@!P bra W_%=;\n\t}"
        :: "r"(mbar), "r"(parity) : "memory");
}

__global__ __launch_bounds__(NTHR, 1) __cluster_dims__(CLUSTER, 1, 1)
void ealstm_kernel(const float* __restrict__ x_dyn,  const float* __restrict__ x_stat,
                   const float* __restrict__ W_i,    const float* __restrict__ b_i,
                   const float* __restrict__ W_f,    const float* __restrict__ b_f,
                   const float* __restrict__ W_g,    const float* __restrict__ b_g,
                   const float* __restrict__ W_o,    const float* __restrict__ b_o,
                   const float* __restrict__ W_head, const float* __restrict__ b_head,
                   float* __restrict__ out)
{
    const int bi   = blockIdx.x >> 3;     // batch group 0..15 (== cluster id)
    const int cj   = blockIdx.x & 7;      // cluster rank = column tile 0..7
    const int tid  = threadIdx.x;
    const int col  = tid & 31;            // local h-column (lane)
    const int rg   = tid >> 5;            // warp id = row group (8 rows each)
    const int row0 = bi * BT;
    const int colg = cj * HC + col;

    // SMEM layout (float4 units):
    //   hs4  [64][64]      h tile (bulk-copied each step)       64 KB
    //   wf4/wg4/wo4 [64][32] recurrent weights, k-major         96 KB
    //   wxf4/wxg4/wxo4 [2][32] x-part weights (k padded to 8)    3 KB
    //   xs4  [2 buf][64][2]  x tile, double buffered             4 KB
    //   mbar
    extern __shared__ float4 smem4[];
    float4* hs4  = smem4;
    float4* wf4  = hs4  + BT * 64;
    float4* wg4  = wf4  + KQH * HC;
    float4* wo4  = wg4  + KQH * HC;
    float4* wxf4 = wo4  + KQH * HC;
    float4* wxg4 = wxf4 + KQX * HC;
    float4* wxo4 = wxg4 + KQX * HC;
    float4* xs4  = wxo4 + KQX * HC;           // [2][BT*2]
    unsigned long long* mbar = (unsigned long long*)(xs4 + 2 * BT * 2);

    const unsigned mbar_a = smem_u32(mbar);
    const unsigned hs_a   = smem_u32(hs4);

    // ---- one-time: weights -> SMEM (k-major) ----
    for (int e = tid; e < KQH * HC; e += NTHR) {
        const int kq = e >> 5, cc = e & 31;
        const int base = (cj * HC + cc) * (DD + HH) + DD + 4 * kq;
        wf4[kq * HC + cc] = make_float4(W_f[base], W_f[base+1], W_f[base+2], W_f[base+3]);
        wg4[kq * HC + cc] = make_float4(W_g[base], W_g[base+1], W_g[base+2], W_g[base+3]);
        wo4[kq * HC + cc] = make_float4(W_o[base], W_o[base+1], W_o[base+2], W_o[base+3]);
    }
    if (tid < KQX * HC) {
        const int kq = tid >> 5, cc = tid & 31;
        const int base = (cj * HC + cc) * (DD + HH);
        if (kq == 0) {
            wxf4[cc] = make_float4(W_f[base], W_f[base+1], W_f[base+2], W_f[base+3]);
            wxg4[cc] = make_float4(W_g[base], W_g[base+1], W_g[base+2], W_g[base+3]);
            wxo4[cc] = make_float4(W_o[base], W_o[base+1], W_o[base+2], W_o[base+3]);
        } else {
            wxf4[HC + cc] = make_float4(W_f[base+4], 0.f, 0.f, 0.f);
            wxg4[HC + cc] = make_float4(W_g[base+4], 0.f, 0.f, 0.f);
            wxo4[HC + cc] = make_float4(W_o[base+4], 0.f, 0.f, 0.f);
        }
    }
    if (tid == 0) {
        asm volatile("mbarrier.init.shared.b64 [%0], 1;" :: "r"(mbar_a) : "memory");
        asm volatile("fence.proxy.async.shared::cta;" ::: "memory");
    }
    __syncthreads();

    // ---- per-thread constants ----
    const float bf_ = __ldg(&b_f[colg]);
    const float bg_ = __ldg(&b_g[colg]);
    const float bo_ = __ldg(&b_o[colg]);

    // static input gate + cell state, 8 cells/thread
    float ig[8], cst[8];
    {
        const float bi_ = __ldg(&b_i[colg]);
#pragma unroll
        for (int j = 0; j < 8; j++) {
            const int r = row0 + rg * 8 + j;
            float s = bi_;
            for (int ss = 0; ss < SS; ss++)
                s = fmaf(__ldg(&x_stat[r * SS + ss]), __ldg(&W_i[colg * SS + ss]), s);
            ig[j]  = sigmoidf_(s);
            cst[j] = 0.f;
        }
    }

    // ---- recurrence ----
    unsigned ph = 0;
    for (int t = 0; t < TT; t++) {
        if (t > 0) {
            // peers' h(t-1) visible after the cluster barrier (acquire)
            asm volatile("barrier.cluster.wait.aligned;" ::: "memory");
            if (tid == 0) {
                asm volatile("mbarrier.arrive.expect_tx.shared::cta.b64 _, [%0], %1;"
                             :: "r"(mbar_a), "r"((unsigned)(BT * HH * 4)) : "memory");
                const float* src = &g_h[(t - 1) & 1][row0][0];
                asm volatile(
                    "cp.async.bulk.shared::cluster.global.mbarrier::complete_tx::bytes "
                    "[%0], [%1], %2, [%3];"
                    :: "r"(hs_a), "l"(src), "r"((unsigned)(BT * HH * 4)), "r"(mbar_a)
                    : "memory");
            }
        }

        // stage x_t (double buffered; bulk h copy in flight underneath)
        float4* xsb = xs4 + (t & 1) * (BT * 2);
        if (tid < BT) {
            const float* xp = x_dyn + ((size_t)(row0 + tid) * TT + t) * DD;
            const float x0 = __ldg(xp+0), x1 = __ldg(xp+1), x2 = __ldg(xp+2),
                        x3 = __ldg(xp+3), x4 = __ldg(xp+4);
            xsb[tid * 2]     = make_float4(x0, x1, x2, x3);
            xsb[tid * 2 + 1] = make_float4(x4, 0.f, 0.f, 0.f);
        }
        __syncthreads();

        // accumulators (even/odd k packed), init with bias
        unsigned long long aF[8], aG[8], aO[8];
#pragma unroll
        for (int j = 0; j < 8; j++) {
            aF[j] = pack2(bf_, 0.f);
            aG[j] = pack2(bg_, 0.f);
            aO[j] = pack2(bo_, 0.f);
        }

        // x part of the GEMM (2 kq)
#pragma unroll
        for (int kq = 0; kq < KQX; kq++) {
            const ulonglong2 wfv = *reinterpret_cast<const ulonglong2*>(&wxf4[kq * HC + col]);
            const ulonglong2 wgv = *reinterpret_cast<const ulonglong2*>(&wxg4[kq * HC + col]);
            const ulonglong2 wov = *reinterpret_cast<const ulonglong2*>(&wxo4[kq * HC + col]);
#pragma unroll
            for (int j = 0; j < 8; j++) {
                const ulonglong2 hv =
                    *reinterpret_cast<const ulonglong2*>(&xsb[(rg * 8 + j) * 2 + kq]);
                ffma2(aF[j], hv.x, wfv.x); ffma2(aF[j], hv.y, wfv.y);
                ffma2(aG[j], hv.x, wgv.x); ffma2(aG[j], hv.y, wgv.y);
                ffma2(aO[j], hv.x, wov.x); ffma2(aO[j], hv.y, wov.y);
            }
        }

        if (t > 0) {
            // h tile arrived?
            mbar_wait(mbar_a, ph);
            ph ^= 1;

            // 64x96x256 tile GEMM: lane=col (conflict-free weight LDS),
            // h rows broadcast. FFMA2 packs (even k, odd k).
#pragma unroll 2
            for (int kq = 0; kq < KQH; kq++) {
                const ulonglong2 wfv = *reinterpret_cast<const ulonglong2*>(&wf4[kq * HC + col]);
                const ulonglong2 wgv = *reinterpret_cast<const ulonglong2*>(&wg4[kq * HC + col]);
                const ulonglong2 wov = *reinterpret_cast<const ulonglong2*>(&wo4[kq * HC + col]);
#pragma unroll
                for (int j = 0; j < 8; j++) {
                    const ulonglong2 hv =
                        *reinterpret_cast<const ulonglong2*>(&hs4[(rg * 8 + j) * 64 + kq]);
                    ffma2(aF[j], hv.x, wfv.x); ffma2(aF[j], hv.y, wfv.y);
                    ffma2(aG[j], hv.x, wgv.x); ffma2(aG[j], hv.y, wgv.y);
                    ffma2(aO[j], hv.x, wov.x); ffma2(aO[j], hv.y, wov.y);
                }
            }
        }

        // epilogue: gates, cell update, publish h slice
        const int wb = t & 1;
#pragma unroll
        for (int j = 0; j < 8; j++) {
            float lo, hi;
            unpack2(aF[j], lo, hi); const float f = sigmoidf_(lo + hi);
            unpack2(aG[j], lo, hi); const float g = tanhf_(lo + hi);
            unpack2(aO[j], lo, hi); const float o = sigmoidf_(lo + hi);
            const float cn = fmaf(f, cst[j], ig[j] * g);
            cst[j] = cn;
            __stcg(&g_h[wb][row0 + rg * 8 + j][colg], o * tanhf_(cn));
        }
        // make stores visible to the async (bulk-copy) proxy, then release
        asm volatile("fence.proxy.async.global;" ::: "memory");
        asm volatile("barrier.cluster.arrive.aligned;" ::: "memory");
    }

    // pairs with the final arrive; peers' last h slices now visible
    asm volatile("barrier.cluster.wait.aligned;" ::: "memory");

    // ---- head: out[b] = h_T[b] . W_head + b_head (rank 0 only) ----
    if (cj == 0) {
        const int row  = tid >> 2, part = tid & 3;
        const int r    = row0 + row;
        const float* hp = &g_h[(TT - 1) & 1][r][0];
        float s = 0.f;
        for (int k = part * 64; k < part * 64 + 64; k++)
            s = fmaf(__ldcg(hp + k), __ldg(&W_head[k]), s);
        s += __shfl_xor_sync(0xffffffffu, s, 1);
        s += __shfl_xor_sync(0xffffffffu, s, 2);
        if (part == 0) out[r] = s + __ldg(&b_head[0]);
    }
}

extern "C" void kernel_launch(void* const* d_in, const int* in_sizes, int n_in,
                              void* d_out, int out_size) {
    (void)in_sizes; (void)n_in; (void)out_size;
    const size_t smem_bytes =
        (size_t)(BT * 64 + 3 * KQH * HC + 3 * KQX * HC + 2 * BT * 2) * sizeof(float4) + 32;
    cudaFuncSetAttribute(ealstm_kernel,
                         cudaFuncAttributeMaxDynamicSharedMemorySize,
                         (int)smem_bytes);
    ealstm_kernel<<<NCTA, NTHR, smem_bytes>>>(
        (const float*)d_in[0],  (const float*)d_in[1],
        (const float*)d_in[2],  (const float*)d_in[3],
        (const float*)d_in[4],  (const float*)d_in[5],
        (const float*)d_in[6],  (const float*)d_in[7],
        (const float*)d_in[8],  (const float*)d_in[9],
        (const float*)d_in[10], (const float*)d_in[11],
        (float*)d_out);
}

// round 5
// speedup vs baseline: 1.1632x; 1.1632x over previous
#include <cuda_runtime.h>
#include <cstdint>

// Problem constants
#define BQ 1024
#define TT 365
#define DD 5
#define SS 27
#define HH 256

// Tiling
#define BT   64    // batch rows per group
#define HC   32    // h-columns per CTA (per gate)
#define GROUPS 16  // batch groups (1024/64)
#define CPG    8   // CTAs per group (256/32)
#define NCTA 128
#define NTHR 256

// Padded k layout: kq 0..1 = x (5 + 3 zeros), kq 0..63 (h part) = 256 h cols
#define KQX 2
#define KQH 64

// Global state (allocation-free scratch)
__device__ float    g_h[2][BQ][HH];          // double-buffered hidden state
__device__ unsigned g_cnt[GROUPS * 32];       // padded barrier counters
__device__ unsigned g_done[GROUPS * 32];      // end-of-kernel reset coordination

// ---- packed fp32x2 helpers (Blackwell FFMA2: 2x fp32 throughput) ----
__device__ __forceinline__ unsigned long long pack2(float lo, float hi) {
    unsigned long long r;
    asm("mov.b64 %0, {%1,%2};" : "=l"(r) : "f"(lo), "f"(hi));
    return r;
}
__device__ __forceinline__ void unpack2(unsigned long long v, float &lo, float &hi) {
    asm("mov.b64 {%0,%1}, %2;" : "=f"(lo), "=f"(hi) : "l"(v));
}
__device__ __forceinline__ void ffma2(unsigned long long &d,
                                      unsigned long long a,
                                      unsigned long long b) {
    asm("fma.rn.f32x2 %0, %1, %2, %0;" : "+l"(d) : "l"(a), "l"(b));
}

__device__ __forceinline__ float sigmoidf_(float x) {
    return 1.f / (1.f + __expf(-x));
}
__device__ __forceinline__ float tanhf_(float x) {
    float e = __expf(-2.f * fabsf(x));   // e in (0,1], no overflow
    float r = (1.f - e) / (1.f + e);
    return copysignf(r, x);
}

// Barrier among the 8 CTAs of one batch group (monotonic counter, proven in R2).
__device__ __forceinline__ void group_barrier(int bi, unsigned phase) {
    __threadfence();
    __syncthreads();
    if (threadIdx.x == 0) {
        atomicAdd(&g_cnt[bi * 32], 1u);
        while (atomicAdd(&g_cnt[bi * 32], 0u) < (unsigned)CPG * phase)
            __nanosleep(32);
    }
    __syncthreads();
}

__global__ __launch_bounds__(NTHR, 1)
void ealstm_kernel(const float* __restrict__ x_dyn,  const float* __restrict__ x_stat,
                   const float* __restrict__ W_i,    const float* __restrict__ b_i,
                   const float* __restrict__ W_f,    const float* __restrict__ b_f,
                   const float* __restrict__ W_g,    const float* __restrict__ b_g,
                   const float* __restrict__ W_o,    const float* __restrict__ b_o,
                   const float* __restrict__ W_head, const float* __restrict__ b_head,
                   float* __restrict__ out)
{
    const int bi   = blockIdx.x >> 3;     // batch group 0..15
    const int cj   = blockIdx.x & 7;      // column tile 0..7
    const int tid  = threadIdx.x;
    const int col  = tid & 31;            // local h-column (lane)
    const int rg   = tid >> 5;            // warp id = row group (8 rows each)
    const int row0 = bi * BT;
    const int colg = cj * HC + col;

    // SMEM (float4 units): h tile, 3 recurrent weight slices (k-major),
    // 3 x-part weight slices, x tile.
    extern __shared__ float4 smem4[];
    float4* hs4  = smem4;                 // [BT][64]        64 KB
    float4* wf4  = hs4  + BT * 64;        // [KQH][HC]       32 KB
    float4* wg4  = wf4  + KQH * HC;       //                 32 KB
    float4* wo4  = wg4  + KQH * HC;       //                 32 KB
    float4* wxf4 = wo4  + KQH * HC;       // [KQX][HC]        1 KB
    float4* wxg4 = wxf4 + KQX * HC;
    float4* wxo4 = wxg4 + KQX * HC;
    float4* xs4  = wxo4 + KQX * HC;       // [BT][2]          2 KB

    // ---- one-time: weights -> SMEM (k-major) ----
    for (int e = tid; e < KQH * HC; e += NTHR) {
        const int kq = e >> 5, cc = e & 31;
        const int base = (cj * HC + cc) * (DD + HH) + DD + 4 * kq;
        wf4[kq * HC + cc] = make_float4(W_f[base], W_f[base+1], W_f[base+2], W_f[base+3]);
        wg4[kq * HC + cc] = make_float4(W_g[base], W_g[base+1], W_g[base+2], W_g[base+3]);
        wo4[kq * HC + cc] = make_float4(W_o[base], W_o[base+1], W_o[base+2], W_o[base+3]);
    }
    if (tid < KQX * HC) {
        const int kq = tid >> 5, cc = tid & 31;
        const int base = (cj * HC + cc) * (DD + HH);
        if (kq == 0) {
            wxf4[cc] = make_float4(W_f[base], W_f[base+1], W_f[base+2], W_f[base+3]);
            wxg4[cc] = make_float4(W_g[base], W_g[base+1], W_g[base+2], W_g[base+3]);
            wxo4[cc] = make_float4(W_o[base], W_o[base+1], W_o[base+2], W_o[base+3]);
        } else {
            wxf4[HC + cc] = make_float4(W_f[base+4], 0.f, 0.f, 0.f);
            wxg4[HC + cc] = make_float4(W_g[base+4], 0.f, 0.f, 0.f);
            wxo4[HC + cc] = make_float4(W_o[base+4], 0.f, 0.f, 0.f);
        }
    }
    __syncthreads();

    // ---- per-thread constants ----
    const float bf_ = __ldg(&b_f[colg]);
    const float bg_ = __ldg(&b_g[colg]);
    const float bo_ = __ldg(&b_o[colg]);

    // static input gate + cell state, 8 (row,col) cells per thread
    float ig[8], cst[8];
    {
        const float bi_ = __ldg(&b_i[colg]);
#pragma unroll
        for (int j = 0; j < 8; j++) {
            const int r = row0 + rg * 8 + j;
            float s = bi_;
            for (int ss = 0; ss < SS; ss++)
                s = fmaf(__ldg(&x_stat[r * SS + ss]), __ldg(&W_i[colg * SS + ss]), s);
            ig[j]  = sigmoidf_(s);
            cst[j] = 0.f;
        }
    }

    // ---- recurrence ----
    unsigned phase = 0;
    for (int t = 0; t < TT; t++) {
        if (t > 0) {
            phase++;
            group_barrier(bi, phase);
            // stage h tile (L2-coherent) into SMEM; x LDG below overlaps this
            const float4* src = reinterpret_cast<const float4*>(&g_h[(t - 1) & 1][row0][0]);
            for (int e = tid; e < BT * 64; e += NTHR)
                hs4[e] = __ldcg(src + e);
        }
        // stage x_t (single buffer: all threads are past step t-1 here)
        if (tid < BT) {
            const float* xp = x_dyn + ((size_t)(row0 + tid) * TT + t) * DD;
            const float x0 = __ldg(xp+0), x1 = __ldg(xp+1), x2 = __ldg(xp+2),
                        x3 = __ldg(xp+3), x4 = __ldg(xp+4);
            xs4[tid * 2]     = make_float4(x0, x1, x2, x3);
            xs4[tid * 2 + 1] = make_float4(x4, 0.f, 0.f, 0.f);
        }
        __syncthreads();

        // accumulators (even/odd k packed), init with bias
        unsigned long long aF[8], aG[8], aO[8];
#pragma unroll
        for (int j = 0; j < 8; j++) {
            aF[j] = pack2(bf_, 0.f);
            aG[j] = pack2(bg_, 0.f);
            aO[j] = pack2(bo_, 0.f);
        }

        // x part of the fused GEMM (2 kq)
#pragma unroll
        for (int kq = 0; kq < KQX; kq++) {
            const ulonglong2 wfv = *reinterpret_cast<const ulonglong2*>(&wxf4[kq * HC + col]);
            const ulonglong2 wgv = *reinterpret_cast<const ulonglong2*>(&wxg4[kq * HC + col]);
            const ulonglong2 wov = *reinterpret_cast<const ulonglong2*>(&wxo4[kq * HC + col]);
#pragma unroll
            for (int j = 0; j < 8; j++) {
                const ulonglong2 xv =
                    *reinterpret_cast<const ulonglong2*>(&xs4[(rg * 8 + j) * 2 + kq]);
                ffma2(aF[j], xv.x, wfv.x); ffma2(aF[j], xv.y, wfv.y);
                ffma2(aG[j], xv.x, wgv.x); ffma2(aG[j], xv.y, wgv.y);
                ffma2(aO[j], xv.x, wov.x); ffma2(aO[j], xv.y, wov.y);
            }
        }

        if (t > 0) {
            // 64x96x256 tile GEMM: lane=col (conflict-free weight LDS),
            // h rows broadcast. FFMA2 packs (even k, odd k).
#pragma unroll 2
            for (int kq = 0; kq < KQH; kq++) {
                const ulonglong2 wfv = *reinterpret_cast<const ulonglong2*>(&wf4[kq * HC + col]);
                const ulonglong2 wgv = *reinterpret_cast<const ulonglong2*>(&wg4[kq * HC + col]);
                const ulonglong2 wov = *reinterpret_cast<const ulonglong2*>(&wo4[kq * HC + col]);
#pragma unroll
                for (int j = 0; j < 8; j++) {
                    const ulonglong2 hv =
                        *reinterpret_cast<const ulonglong2*>(&hs4[(rg * 8 + j) * 64 + kq]);
                    ffma2(aF[j], hv.x, wfv.x); ffma2(aF[j], hv.y, wfv.y);
                    ffma2(aG[j], hv.x, wgv.x); ffma2(aG[j], hv.y, wgv.y);
                    ffma2(aO[j], hv.x, wov.x); ffma2(aO[j], hv.y, wov.y);
                }
            }
        }

        // epilogue: gates, cell update, publish h slice (L2-coherent)
        const int wb = t & 1;
#pragma unroll
        for (int j = 0; j < 8; j++) {
            float lo, hi;
            unpack2(aF[j], lo, hi); const float f = sigmoidf_(lo + hi);
            unpack2(aG[j], lo, hi); const float g = tanhf_(lo + hi);
            unpack2(aO[j], lo, hi); const float o = sigmoidf_(lo + hi);
            const float cn = fmaf(f, cst[j], ig[j] * g);
            cst[j] = cn;
            __stcg(&g_h[wb][row0 + rg * 8 + j][colg], o * tanhf_(cn));
        }
    }

    // ---- head: out[b] = h_T[b] . W_head + b_head ----
    phase++;
    group_barrier(bi, phase);
    if (cj == 0) {
        const int row  = tid >> 2, part = tid & 3;
        const int r    = row0 + row;
        const float* hp = &g_h[(TT - 1) & 1][r][0];
        float s = 0.f;
        for (int k = part * 64; k < part * 64 + 64; k++)
            s = fmaf(__ldcg(hp + k), __ldg(&W_head[k]), s);
        s += __shfl_xor_sync(0xffffffffu, s, 1);
        s += __shfl_xor_sync(0xffffffffu, s, 2);
        if (part == 0) out[r] = s + __ldg(&b_head[0]);
    }

    // ---- reset barrier counters so graph replays are deterministic ----
    __syncthreads();
    if (tid == 0) {
        __threadfence();
        atomicAdd(&g_done[bi * 32], 1u);
        if (cj == 0) {
            while (atomicAdd(&g_done[bi * 32], 0u) < CPG) __nanosleep(64);
            atomicExch(&g_cnt[bi * 32], 0u);
            atomicExch(&g_done[bi * 32], 0u);
        }
    }
}

extern "C" void kernel_launch(void* const* d_in, const int* in_sizes, int n_in,
                              void* d_out, int out_size) {
    (void)in_sizes; (void)n_in; (void)out_size;
    const size_t smem_bytes =
        (size_t)(BT * 64 + 3 * KQH * HC + 3 * KQX * HC + BT * 2) * sizeof(float4);
    cudaFuncSetAttribute(ealstm_kernel,
                         cudaFuncAttributeMaxDynamicSharedMemorySize,
                         (int)smem_bytes);
    ealstm_kernel<<<NCTA, NTHR, smem_bytes>>>(
        (const float*)d_in[0],  (const float*)d_in[1],
        (const float*)d_in[2],  (const float*)d_in[3],
        (const float*)d_in[4],  (const float*)d_in[5],
        (const float*)d_in[6],  (const float*)d_in[7],
        (const float*)d_in[8],  (const float*)d_in[9],
        (const float*)d_in[10], (const float*)d_in[11],
        (float*)d_out);
}

// round 6
// speedup vs baseline: 1.8637x; 1.6021x over previous
#include <cuda_runtime.h>
#include <cstdint>

// Problem constants
#define BQ 1024
#define TT 365
#define DD 5
#define SS 27
#define HH 256

// Tiling
#define BT   64    // batch rows per group
#define HC   32    // h-columns per CTA (per gate)
#define GROUPS 16  // batch groups (1024/64)
#define CPG    8   // CTAs per group (256/32)
#define NCTA 128
#define NTHR 256

// Padded k layout: kq 0..1 = x (5 + 3 zeros), kq 0..63 (h part) = 256 h cols
#define KQX 2
#define KQH 64

// Global state (allocation-free scratch)
__device__ float    g_h[2][BQ][HH];          // double-buffered hidden state
__device__ unsigned g_cnt[GROUPS * 32];       // padded barrier counters
__device__ unsigned g_done[GROUPS * 32];      // end-of-kernel reset coordination

// ---- packed fp32x2 helpers (Blackwell FFMA2: 2x fp32 throughput) ----
__device__ __forceinline__ unsigned long long pack2(float lo, float hi) {
    unsigned long long r;
    asm("mov.b64 %0, {%1,%2};" : "=l"(r) : "f"(lo), "f"(hi));
    return r;
}
__device__ __forceinline__ void unpack2(unsigned long long v, float &lo, float &hi) {
    asm("mov.b64 {%0,%1}, %2;" : "=f"(lo), "=f"(hi) : "l"(v));
}
__device__ __forceinline__ void ffma2(unsigned long long &d,
                                      unsigned long long a,
                                      unsigned long long b) {
    asm("fma.rn.f32x2 %0, %1, %2, %0;" : "+l"(d) : "l"(a), "l"(b));
}

__device__ __forceinline__ float sigmoidf_(float x) {
    return 1.f / (1.f + __expf(-x));
}
__device__ __forceinline__ float tanhf_(float x) {
    float e = __expf(-2.f * fabsf(x));   // e in (0,1], no overflow
    float r = (1.f - e) / (1.f + e);
    return copysignf(r, x);
}

// Barrier among the 8 CTAs of one batch group (monotonic counter, proven in R2).
__device__ __forceinline__ void group_barrier(int bi, unsigned phase) {
    __threadfence();
    __syncthreads();
    if (threadIdx.x == 0) {
        atomicAdd(&g_cnt[bi * 32], 1u);
        while (atomicAdd(&g_cnt[bi * 32], 0u) < (unsigned)CPG * phase)
            __nanosleep(32);
    }
    __syncthreads();
}

__global__ __launch_bounds__(NTHR, 1)
void ealstm_kernel(const float* __restrict__ x_dyn,  const float* __restrict__ x_stat,
                   const float* __restrict__ W_i,    const float* __restrict__ b_i,
                   const float* __restrict__ W_f,    const float* __restrict__ b_f,
                   const float* __restrict__ W_g,    const float* __restrict__ b_g,
                   const float* __restrict__ W_o,    const float* __restrict__ b_o,
                   const float* __restrict__ W_head, const float* __restrict__ b_head,
                   float* __restrict__ out)
{
    const int bi   = blockIdx.x >> 3;     // batch group 0..15
    const int cj   = blockIdx.x & 7;      // column tile 0..7
    const int tid  = threadIdx.x;
    const int col  = tid & 31;            // local h-column (lane)
    const int rg   = tid >> 5;            // warp id = row group (8 rows each)
    const int row0 = bi * BT;
    const int colg = cj * HC + col;

    // SMEM (float4 units): h tile, 3 recurrent weight slices (k-major),
    // 3 x-part weight slices, x tile.
    extern __shared__ float4 smem4[];
    float4* hs4  = smem4;                 // [BT][64]        64 KB
    float4* wf4  = hs4  + BT * 64;        // [KQH][HC]       32 KB
    float4* wg4  = wf4  + KQH * HC;       //                 32 KB
    float4* wo4  = wg4  + KQH * HC;       //                 32 KB
    float4* wxf4 = wo4  + KQH * HC;       // [KQX][HC]        1 KB
    float4* wxg4 = wxf4 + KQX * HC;
    float4* wxo4 = wxg4 + KQX * HC;
    float4* xs4  = wxo4 + KQX * HC;       // [BT][2]          2 KB

    // ---- one-time: weights -> SMEM (k-major) ----
    for (int e = tid; e < KQH * HC; e += NTHR) {
        const int kq = e >> 5, cc = e & 31;
        const int base = (cj * HC + cc) * (DD + HH) + DD + 4 * kq;
        wf4[kq * HC + cc] = make_float4(W_f[base], W_f[base+1], W_f[base+2], W_f[base+3]);
        wg4[kq * HC + cc] = make_float4(W_g[base], W_g[base+1], W_g[base+2], W_g[base+3]);
        wo4[kq * HC + cc] = make_float4(W_o[base], W_o[base+1], W_o[base+2], W_o[base+3]);
    }
    if (tid < KQX * HC) {
        const int kq = tid >> 5, cc = tid & 31;
        const int base = (cj * HC + cc) * (DD + HH);
        if (kq == 0) {
            wxf4[cc] = make_float4(W_f[base], W_f[base+1], W_f[base+2], W_f[base+3]);
            wxg4[cc] = make_float4(W_g[base], W_g[base+1], W_g[base+2], W_g[base+3]);
            wxo4[cc] = make_float4(W_o[base], W_o[base+1], W_o[base+2], W_o[base+3]);
        } else {
            wxf4[HC + cc] = make_float4(W_f[base+4], 0.f, 0.f, 0.f);
            wxg4[HC + cc] = make_float4(W_g[base+4], 0.f, 0.f, 0.f);
            wxo4[HC + cc] = make_float4(W_o[base+4], 0.f, 0.f, 0.f);
        }
    }
    __syncthreads();

    // ---- per-thread constants ----
    const float bf_ = __ldg(&b_f[colg]);
    const float bg_ = __ldg(&b_g[colg]);
    const float bo_ = __ldg(&b_o[colg]);

    // static input gate + cell state, 8 (row,col) cells per thread
    float ig[8], cst[8];
    {
        const float bi_ = __ldg(&b_i[colg]);
#pragma unroll
        for (int j = 0; j < 8; j++) {
            const int r = row0 + rg * 8 + j;
            float s = bi_;
            for (int ss = 0; ss < SS; ss++)
                s = fmaf(__ldg(&x_stat[r * SS + ss]), __ldg(&W_i[colg * SS + ss]), s);
            ig[j]  = sigmoidf_(s);
            cst[j] = 0.f;
        }
    }

    // ---- recurrence ----
    unsigned phase = 0;
    for (int t = 0; t < TT; t++) {
        if (t > 0) {
            phase++;
            group_barrier(bi, phase);
            // stage h tile (L2-coherent) into SMEM; x LDG below overlaps this
            const float4* src = reinterpret_cast<const float4*>(&g_h[(t - 1) & 1][row0][0]);
            for (int e = tid; e < BT * 64; e += NTHR)
                hs4[e] = __ldcg(src + e);
        }
        // stage x_t (single buffer: all threads are past step t-1 here)
        if (tid < BT) {
            const float* xp = x_dyn + ((size_t)(row0 + tid) * TT + t) * DD;
            const float x0 = __ldg(xp+0), x1 = __ldg(xp+1), x2 = __ldg(xp+2),
                        x3 = __ldg(xp+3), x4 = __ldg(xp+4);
            xs4[tid * 2]     = make_float4(x0, x1, x2, x3);
            xs4[tid * 2 + 1] = make_float4(x4, 0.f, 0.f, 0.f);
        }
        __syncthreads();

        // accumulators (even/odd k packed), init with bias
        unsigned long long aF[8], aG[8], aO[8];
#pragma unroll
        for (int j = 0; j < 8; j++) {
            aF[j] = pack2(bf_, 0.f);
            aG[j] = pack2(bg_, 0.f);
            aO[j] = pack2(bo_, 0.f);
        }

        // x part of the fused GEMM (2 kq)
#pragma unroll
        for (int kq = 0; kq < KQX; kq++) {
            const ulonglong2 wfv = *reinterpret_cast<const ulonglong2*>(&wxf4[kq * HC + col]);
            const ulonglong2 wgv = *reinterpret_cast<const ulonglong2*>(&wxg4[kq * HC + col]);
            const ulonglong2 wov = *reinterpret_cast<const ulonglong2*>(&wxo4[kq * HC + col]);
#pragma unroll
            for (int j = 0; j < 8; j++) {
                const ulonglong2 xv =
                    *reinterpret_cast<const ulonglong2*>(&xs4[(rg * 8 + j) * 2 + kq]);
                ffma2(aF[j], xv.x, wfv.x); ffma2(aF[j], xv.y, wfv.y);
                ffma2(aG[j], xv.x, wgv.x); ffma2(aG[j], xv.y, wgv.y);
                ffma2(aO[j], xv.x, wov.x); ffma2(aO[j], xv.y, wov.y);
            }
        }

        if (t > 0) {
            // 64x96x256 tile GEMM: lane=col (conflict-free weight LDS),
            // h rows broadcast. FFMA2 packs (even k, odd k).
#pragma unroll 2
            for (int kq = 0; kq < KQH; kq++) {
                const ulonglong2 wfv = *reinterpret_cast<const ulonglong2*>(&wf4[kq * HC + col]);
                const ulonglong2 wgv = *reinterpret_cast<const ulonglong2*>(&wg4[kq * HC + col]);
                const ulonglong2 wov = *reinterpret_cast<const ulonglong2*>(&wo4[kq * HC + col]);
#pragma unroll
                for (int j = 0; j < 8; j++) {
                    const ulonglong2 hv =
                        *reinterpret_cast<const ulonglong2*>(&hs4[(rg * 8 + j) * 64 + kq]);
                    ffma2(aF[j], hv.x, wfv.x); ffma2(aF[j], hv.y, wfv.y);
                    ffma2(aG[j], hv.x, wgv.x); ffma2(aG[j], hv.y, wgv.y);
                    ffma2(aO[j], hv.x, wov.x); ffma2(aO[j], hv.y, wov.y);
                }
            }
        }

        // epilogue: gates, cell update, publish h slice (L2-coherent)
        const int wb = t & 1;
#pragma unroll
        for (int j = 0; j < 8; j++) {
            float lo, hi;
            unpack2(aF[j], lo, hi); const float f = sigmoidf_(lo + hi);
            unpack2(aG[j], lo, hi); const float g = tanhf_(lo + hi);
            unpack2(aO[j], lo, hi); const float o = sigmoidf_(lo + hi);
            const float cn = fmaf(f, cst[j], ig[j] * g);
            cst[j] = cn;
            __stcg(&g_h[wb][row0 + rg * 8 + j][colg], o * tanhf_(cn));
        }
    }

    // ---- head: out[b] = h_T[b] . W_head + b_head ----
    phase++;
    group_barrier(bi, phase);
    if (cj == 0) {
        const int row  = tid >> 2, part = tid & 3;
        const int r    = row0 + row;
        const float* hp = &g_h[(TT - 1) & 1][r][0];
        float s = 0.f;
        for (int k = part * 64; k < part * 64 + 64; k++)
            s = fmaf(__ldcg(hp + k), __ldg(&W_head[k]), s);
        s += __shfl_xor_sync(0xffffffffu, s, 1);
        s += __shfl_xor_sync(0xffffffffu, s, 2);
        if (part == 0) out[r] = s + __ldg(&b_head[0]);
    }

    // ---- reset barrier counters so graph replays are deterministic ----
    __syncthreads();
    if (tid == 0) {
        __threadfence();
        atomicAdd(&g_done[bi * 32], 1u);
        if (cj == 0) {
            while (atomicAdd(&g_done[bi * 32], 0u) < CPG) __nanosleep(64);
            atomicExch(&g_cnt[bi * 32], 0u);
            atomicExch(&g_done[bi * 32], 0u);
        }
    }
}

extern "C" void kernel_launch(void* const* d_in, const int* in_sizes, int n_in,
                              void* d_out, int out_size) {
    (void)in_sizes; (void)n_in; (void)out_size;
    const size_t smem_bytes =
        (size_t)(BT * 64 + 3 * KQH * HC + 3 * KQX * HC + BT * 2) * sizeof(float4);
    cudaFuncSetAttribute(ealstm_kernel,
                         cudaFuncAttributeMaxDynamicSharedMemorySize,
                         (int)smem_bytes);
    ealstm_kernel<<<NCTA, NTHR, smem_bytes>>>(
        (const float*)d_in[0],  (const float*)d_in[1],
        (const float*)d_in[2],  (const float*)d_in[3],
        (const float*)d_in[4],  (const float*)d_in[5],
        (const float*)d_in[6],  (const float*)d_in[7],
        (const float*)d_in[8],  (const float*)d_in[9],
        (const float*)d_in[10], (const float*)d_in[11],
        (float*)d_out);
}